// round 7
// baseline (speedup 1.0000x reference)
#include <cuda_runtime.h>

// IndRNN recurrence: h_t = relu(h_{t-1} * w[h] + x[t,b,h]), out[t,b,h] = h_t
// x: [T, B, H] fp32, w: [H], h0: [B, H], out: [T, B, H]. T=1024, B=64, H=1024.
// R6: float4 per thread (16384 threads, LDG.128/STG.128) + PF=16 prefetch
// ring + streaming hints. R5 proved the lever is requests-per-byte (float2 +
// __ldcs/__stcs: 99->84.7us, DRAM 67->79%); this halves request count again.

#define T_STEPS 1024
#define B_DIM 64
#define H_DIM 1024
#define BH (B_DIM * H_DIM)
#define BH4 (BH / 4)      // float4 elements per time step
#define H4 (H_DIM / 4)
#define PF 16

__global__ __launch_bounds__(64)
void indrnn_kernel(const float4* __restrict__ x,
                   const float4* __restrict__ w,
                   const float4* __restrict__ h0,
                   float4* __restrict__ out) {
    const int idx = blockIdx.x * blockDim.x + threadIdx.x;  // 0 .. BH4-1
    const int hcol = idx & (H4 - 1);

    const float4 wv = w[hcol];
    float4 h = h0[idx];

    const float4* xp = x + idx;
    float4* op = out + idx;

    float4 buf[PF];

    // Prologue: fill the ring with steps 0..PF-1
    #pragma unroll
    for (int i = 0; i < PF; i++)
        buf[i] = __ldcs(xp + i * BH4);

    const float4* xpre = xp + PF * BH4;

    // Steady state: consume slot i, immediately refill with step t+PF+i.
    #pragma unroll 1
    for (int t = 0; t < T_STEPS - PF; t += PF) {
        #pragma unroll
        for (int i = 0; i < PF; i++) {
            const float4 xv = buf[i];
            buf[i] = __ldcs(xpre + i * BH4);     // prefetch t+PF+i
            h.x = fmaxf(fmaf(h.x, wv.x, xv.x), 0.0f);
            h.y = fmaxf(fmaf(h.y, wv.y, xv.y), 0.0f);
            h.z = fmaxf(fmaf(h.z, wv.z, xv.z), 0.0f);
            h.w = fmaxf(fmaf(h.w, wv.w, xv.w), 0.0f);
            __stcs(op + i * BH4, h);
        }
        xpre += PF * BH4;
        op   += PF * BH4;
    }

    // Epilogue: last PF steps, ring already full
    #pragma unroll
    for (int i = 0; i < PF; i++) {
        const float4 xv = buf[i];
        h.x = fmaxf(fmaf(h.x, wv.x, xv.x), 0.0f);
        h.y = fmaxf(fmaf(h.y, wv.y, xv.y), 0.0f);
        h.z = fmaxf(fmaf(h.z, wv.z, xv.z), 0.0f);
        h.w = fmaxf(fmaf(h.w, wv.w, xv.w), 0.0f);
        __stcs(op + i * BH4, h);
    }
}

extern "C" void kernel_launch(void* const* d_in, const int* in_sizes, int n_in,
                              void* d_out, int out_size) {
    const float4* x  = (const float4*)d_in[0];   // [T, B, H]
    const float4* w  = (const float4*)d_in[1];   // [H]
    const float4* h0 = (const float4*)d_in[2];   // [B, H]
    float4* out = (float4*)d_out;                // [T, B, H]

    const int threads = 64;
    const int blocks = BH4 / threads;            // 256 blocks
    indrnn_kernel<<<blocks, threads>>>(x, w, h0, out);
}

// round 8
// speedup vs baseline: 1.3374x; 1.3374x over previous
#include <cuda_runtime.h>

// IndRNN recurrence: h_t = relu(h_{t-1} * w[h] + x[t,b,h]), out[t,b,h] = h_t
// x: [T, B, H] fp32, w: [H], h0: [B, H], out: [T, B, H]. T=1024, B=64, H=1024.
// R7: R5's float2 + PF=32 ring (best: 84.7us, DRAM 79%), with ONE change:
// __stcs -> __stwt (write-through). Dirty-line evictions from L2 pace the
// write stream poorly (bursty turnarounds); write-through emits stores in
// issue order, smoothing the DRAM write stream. (float4 in R6 regressed:
// warp scarcity + CTA imbalance — requests/byte lever saturated at float2.)

#define T_STEPS 1024
#define B_DIM 64
#define H_DIM 1024
#define BH (B_DIM * H_DIM)
#define BH2 (BH / 2)      // float2 elements per time step
#define H2 (H_DIM / 2)
#define PF 32

__global__ __launch_bounds__(64)
void indrnn_kernel(const float2* __restrict__ x,
                   const float2* __restrict__ w,
                   const float2* __restrict__ h0,
                   float2* __restrict__ out) {
    const int idx = blockIdx.x * blockDim.x + threadIdx.x;  // 0 .. BH2-1
    const int hcol = idx & (H2 - 1);

    const float2 wv = w[hcol];
    float2 h = h0[idx];

    const float2* xp = x + idx;
    float2* op = out + idx;

    float2 buf[PF];

    // Prologue: fill the ring with steps 0..PF-1
    #pragma unroll
    for (int i = 0; i < PF; i++)
        buf[i] = __ldcs(xp + i * BH2);

    const float2* xpre = xp + PF * BH2;

    // Steady state: consume slot i, immediately refill with step t+PF+i.
    #pragma unroll 1
    for (int t = 0; t < T_STEPS - PF; t += PF) {
        #pragma unroll
        for (int i = 0; i < PF; i++) {
            const float2 xv = buf[i];
            buf[i] = __ldcs(xpre + i * BH2);     // prefetch t+PF+i
            h.x = fmaxf(fmaf(h.x, wv.x, xv.x), 0.0f);
            h.y = fmaxf(fmaf(h.y, wv.y, xv.y), 0.0f);
            __stwt(op + i * BH2, h);
        }
        xpre += PF * BH2;
        op   += PF * BH2;
    }

    // Epilogue: last PF steps, ring already full
    #pragma unroll
    for (int i = 0; i < PF; i++) {
        const float2 xv = buf[i];
        h.x = fmaxf(fmaf(h.x, wv.x, xv.x), 0.0f);
        h.y = fmaxf(fmaf(h.y, wv.y, xv.y), 0.0f);
        __stwt(op + i * BH2, h);
    }
}

extern "C" void kernel_launch(void* const* d_in, const int* in_sizes, int n_in,
                              void* d_out, int out_size) {
    const float2* x  = (const float2*)d_in[0];   // [T, B, H]
    const float2* w  = (const float2*)d_in[1];   // [H]
    const float2* h0 = (const float2*)d_in[2];   // [B, H]
    float2* out = (float2*)d_out;                // [T, B, H]

    const int threads = 64;
    const int blocks = BH2 / threads;            // 512 blocks
    indrnn_kernel<<<blocks, threads>>>(x, w, h0, out);
}

// round 9
// speedup vs baseline: 1.3705x; 1.0248x over previous
#include <cuda_runtime.h>

// IndRNN recurrence: h_t = relu(h_{t-1} * w[h] + x[t,b,h]), out[t,b,h] = h_t
// x: [T, B, H] fp32, w: [H], h0: [B, H], out: [T, B, H]. T=1024, B=64, H=1024.
// R8: R5 config (float2 + PF=32 ring + __ldcs/__stcs, best 84.7us/79% DRAM)
// with 32-thread blocks: 1024 CTAs over 148 SMs -> max 7 vs avg 6.92 CTAs/SM
// (imbalance 1.01) instead of 512 CTAs (4 vs 3.46, tail 1.156). At float1 this
// was hidden behind the request-rate cap; at float2's 79% it should bind.
// (R7 falsified __stwt: L2 dirty-eviction write combining is already good.)

#define T_STEPS 1024
#define B_DIM 64
#define H_DIM 1024
#define BH (B_DIM * H_DIM)
#define BH2 (BH / 2)      // float2 elements per time step
#define H2 (H_DIM / 2)
#define PF 32

__global__ __launch_bounds__(32)
void indrnn_kernel(const float2* __restrict__ x,
                   const float2* __restrict__ w,
                   const float2* __restrict__ h0,
                   float2* __restrict__ out) {
    const int idx = blockIdx.x * blockDim.x + threadIdx.x;  // 0 .. BH2-1
    const int hcol = idx & (H2 - 1);

    const float2 wv = w[hcol];
    float2 h = h0[idx];

    const float2* xp = x + idx;
    float2* op = out + idx;

    float2 buf[PF];

    // Prologue: fill the ring with steps 0..PF-1
    #pragma unroll
    for (int i = 0; i < PF; i++)
        buf[i] = __ldcs(xp + i * BH2);

    const float2* xpre = xp + PF * BH2;

    // Steady state: consume slot i, immediately refill with step t+PF+i.
    #pragma unroll 1
    for (int t = 0; t < T_STEPS - PF; t += PF) {
        #pragma unroll
        for (int i = 0; i < PF; i++) {
            const float2 xv = buf[i];
            buf[i] = __ldcs(xpre + i * BH2);     // prefetch t+PF+i
            h.x = fmaxf(fmaf(h.x, wv.x, xv.x), 0.0f);
            h.y = fmaxf(fmaf(h.y, wv.y, xv.y), 0.0f);
            __stcs(op + i * BH2, h);
        }
        xpre += PF * BH2;
        op   += PF * BH2;
    }

    // Epilogue: last PF steps, ring already full
    #pragma unroll
    for (int i = 0; i < PF; i++) {
        const float2 xv = buf[i];
        h.x = fmaxf(fmaf(h.x, wv.x, xv.x), 0.0f);
        h.y = fmaxf(fmaf(h.y, wv.y, xv.y), 0.0f);
        __stcs(op + i * BH2, h);
    }
}

extern "C" void kernel_launch(void* const* d_in, const int* in_sizes, int n_in,
                              void* d_out, int out_size) {
    const float2* x  = (const float2*)d_in[0];   // [T, B, H]
    const float2* w  = (const float2*)d_in[1];   // [H]
    const float2* h0 = (const float2*)d_in[2];   // [B, H]
    float2* out = (float2*)d_out;                // [T, B, H]

    const int threads = 32;
    const int blocks = BH2 / threads;            // 1024 blocks -> 6.92 CTAs/SM
    indrnn_kernel<<<blocks, threads>>>(x, w, h0, out);
}